// round 14
// baseline (speedup 1.0000x reference)
#include <cuda_runtime.h>
#include <cuda_fp16.h>
#include <cstdint>

#define Bn   2048
#define Nin  512
#define Tn   100
#define H1n  512
#define H2n  256
#define On   5
#define Mn   (Tn*Bn)   // 204800 rows = (t,b)

// ---------------- scratch (device globals: allocation-free) ----------------
__device__ __half g_xh[(size_t)Mn * Nin];
__device__ __half g_xm[(size_t)Mn * Nin];
__device__ float  g_h1[(size_t)Mn * H1n];
__device__ __half g_s1[(size_t)Mn * H1n];
__device__ float  g_h2[(size_t)Mn * H2n];
__device__ __half g_s2[(size_t)Mn * H2n];
__device__ __half g_W1h[H1n * Nin], g_W1m[H1n * Nin];
__device__ __half g_W2h[H2n * H1n], g_W2m[H2n * H1n];

// ---------------- PTX helpers ----------------------------------------------
__device__ __forceinline__ uint32_t smem_u32(const void* p) {
    uint32_t a;
    asm("{ .reg .u64 t; cvta.to.shared.u64 t, %1; cvt.u32.u64 %0, t; }" : "=r"(a) : "l"(p));
    return a;
}
__device__ __forceinline__ void cp16(uint32_t dst, const void* src) {
    asm volatile("cp.async.cg.shared.global [%0], [%1], 16;" :: "r"(dst), "l"(src));
}
__device__ __forceinline__ void ldsm_x4(uint32_t& r0, uint32_t& r1, uint32_t& r2,
                                        uint32_t& r3, uint32_t addr) {
    asm volatile("ldmatrix.sync.aligned.m8n8.x4.shared.b16 {%0,%1,%2,%3}, [%4];"
                 : "=r"(r0), "=r"(r1), "=r"(r2), "=r"(r3) : "r"(addr));
}
__device__ __forceinline__ void mma16816(float& d0, float& d1, float& d2, float& d3,
                                         uint32_t a0, uint32_t a1, uint32_t a2, uint32_t a3,
                                         uint32_t b0, uint32_t b1) {
    asm volatile("mma.sync.aligned.m16n8k16.row.col.f32.f16.f16.f32 "
                 "{%0,%1,%2,%3}, {%4,%5,%6,%7}, {%8,%9}, {%0,%1,%2,%3};"
                 : "+f"(d0), "+f"(d1), "+f"(d2), "+f"(d3)
                 : "r"(a0), "r"(a1), "r"(a2), "r"(a3), "r"(b0), "r"(b1));
}

// ---------------- weight split: fp32 -> fp16 h/m ----------------------------
template <int MODE>
__global__ void k_wsplit(const float* __restrict__ src, int n) {
    int i = blockIdx.x * blockDim.x + threadIdx.x;
    if (i >= n) return;
    float v = src[i];
    __half h = __float2half_rn(v);
    __half m = __float2half_rn(v - __half2float(h));
    if (MODE == 1) { g_W1h[i] = h; g_W1m[i] = m; }
    else           { g_W2h[i] = h; g_W2m[i] = m; }
}

// ---------------- transpose + 2-split x (B,N,T) -> x{h,m}[(t*B+b)*N + n] ----
__global__ void k_transpose(const float* __restrict__ x) {
    __shared__ float tile[32][33];
    int b  = blockIdx.x;
    int n0 = blockIdx.y * 32;
    int t0 = blockIdx.z * 32;
    int tx = threadIdx.x, ty = threadIdx.y;   // 32 x 8
#pragma unroll
    for (int i = 0; i < 4; i++) {
        int n = n0 + ty + i * 8, t = t0 + tx;
        if (t < Tn) tile[ty + i * 8][tx] = x[((size_t)b * Nin + n) * Tn + t];
    }
    __syncthreads();
#pragma unroll
    for (int i = 0; i < 4; i++) {
        int t = t0 + ty + i * 8, n = n0 + tx;
        if (t < Tn) {
            float v = tile[tx][ty + i * 8];
            __half h = __float2half_rn(v);
            __half m = __float2half_rn(v - __half2float(h));
            size_t idx = ((size_t)t * Bn + b) * Nin + n;
            g_xh[idx] = h; g_xm[idx] = m;
        }
    }
}

// ---------------- HMMA fp16 multi-pass GEMM, HIGH-OCCUPANCY -----------------
// Experiment: occupancy axis. CTA tile 64x64, 128 threads (4 warps, 2Mx2N of
// 32x32 warp tiles), ~75 regs -> 6 CTAs/SM = 24 warps (37.5% occ), 6
// independent barrier domains. BK=32, 2-stage cp.async, SROW=40 padded smem.
// ldsm/mma/epilogue mappings identical to the proven rel_err=0 kernels.
#define SROW 40   // fp16/row: 80B, 16B-aligned chunks, ldsm conflict-free

template <int NT, int NPASS, int MODE>
__global__ __launch_bounds__(128, 6) void k_gemm(const float* __restrict__ bias,
                                                 float* __restrict__ C) {
    __shared__ __align__(16) __half sA[2][64 * SROW];
    __shared__ __align__(16) __half sB[2][64 * SROW];

    const int tid = threadIdx.x;
    const int wid = tid >> 5;
    const int lane = tid & 31;
    const int wm = wid & 1;         // m offset wm*32
    const int wn = wid >> 1;        // n offset wn*32
    const size_t m0 = (size_t)blockIdx.y * 64;
    const int n0 = blockIdx.x * 64;

    float d[2][4][4];               // 2 m16-tiles x 4 n8-tiles
#pragma unroll
    for (int i = 0; i < 2; i++)
#pragma unroll
        for (int j = 0; j < 4; j++)
#pragma unroll
            for (int k = 0; k < 4; k++) d[i][j][k] = 0.0f;

    const uint32_t sAb = smem_u32(&sA[0][0]);
    const uint32_t sBb = smem_u32(&sB[0][0]);
    const uint32_t bufstride = 64 * SROW * 2;   // bytes per stage

    auto do_loads = [&](int kc, int buf) {
        int pass = kc >> 4;
        int kb = (kc & 15) * 32;
        const __half *Ap, *Bp;
        if (MODE == 1) {
            Ap = (pass == 2) ? g_xm : g_xh;
            Bp = (pass == 1) ? g_W1m : g_W1h;
        } else {
            Ap = g_s1;
            Bp = (pass == 0) ? g_W2h : g_W2m;
        }
        uint32_t aB = sAb + buf * bufstride;
        uint32_t bB = sBb + buf * bufstride;
        // per operand: 64 rows x 64B = 256 chunks; 2 per thread
#pragma unroll
        for (int j = 0; j < 2; j++) {
            int q = tid + 128 * j;
            int row = q >> 2, ch = q & 3;
            cp16(aB + row * (SROW * 2) + ch * 16,
                 Ap + (m0 + row) * 512 + kb + ch * 8);
            cp16(bB + row * (SROW * 2) + ch * 16,
                 Bp + (size_t)(n0 + row) * 512 + kb + ch * 8);
        }
        asm volatile("cp.async.commit_group;");
    };

    constexpr int KC = NPASS * 16;
    do_loads(0, 0);

    // ldsm per-lane fixed indices (proven mapping)
    const int arow0 = wm * 32 + (lane & 15);
    const int achk  = (lane >> 4) * 16;
    const int g     = lane >> 3;
    const int bchk  = (g & 1) * 16;
    const int brow_base = wn * 32 + (g >> 1) * 8 + (lane & 7);

    for (int kc = 0; kc < KC; kc++) {
        const int buf = kc & 1;
        if (kc + 1 < KC) {
            do_loads(kc + 1, buf ^ 1);
            asm volatile("cp.async.wait_group 1;");
        } else {
            asm volatile("cp.async.wait_group 0;");
        }
        __syncthreads();

        const uint32_t aB = sAb + buf * bufstride;
        const uint32_t bB = sBb + buf * bufstride;
#pragma unroll
        for (int ks = 0; ks < 2; ks++) {
            uint32_t a[2][4];
#pragma unroll
            for (int mt = 0; mt < 2; mt++) {
                int row = arow0 + mt * 16;
                ldsm_x4(a[mt][0], a[mt][1], a[mt][2], a[mt][3],
                        aB + (row * SROW + ks * 16) * 2 + achk);
            }
            uint32_t b[2][4];
#pragma unroll
            for (int p = 0; p < 2; p++) {
                int row = brow_base + p * 16;
                ldsm_x4(b[p][0], b[p][1], b[p][2], b[p][3],
                        bB + (row * SROW + ks * 16) * 2 + bchk);
            }
#pragma unroll
            for (int mt = 0; mt < 2; mt++)
#pragma unroll
                for (int nt = 0; nt < 4; nt++) {
                    int p = nt >> 1, s = nt & 1;
                    mma16816(d[mt][nt][0], d[mt][nt][1], d[mt][nt][2], d[mt][nt][3],
                             a[mt][0], a[mt][1], a[mt][2], a[mt][3],
                             b[p][2 * s], b[p][2 * s + 1]);
                }
        }
        __syncthreads();
    }

    // epilogue: d[mt][nt]{0,1}=row r, {2,3}=row r+8; cols n,n+1
    const int r = lane >> 2, c2 = (lane & 3) * 2;
#pragma unroll
    for (int mt = 0; mt < 2; mt++) {
#pragma unroll
        for (int nt = 0; nt < 4; nt++) {
            int n = n0 + wn * 32 + nt * 8 + c2;
            size_t m = m0 + wm * 32 + mt * 16 + r;
            float bx = bias[n], by = bias[n + 1];
            float2 o0 = { d[mt][nt][0] + bx, d[mt][nt][1] + by };
            float2 o1 = { d[mt][nt][2] + bx, d[mt][nt][3] + by };
            *(float2*)(C + m * NT + n) = o0;
            *(float2*)(C + (m + 8) * NT + n) = o1;
        }
    }
}

// ---------------- LIF over time (h fp32 -> spikes fp16) ---------------------
template <int MODE>
__global__ void k_lif() {
    const float* h;
    __half* s;
    int width;
    if (MODE == 1) { h = g_h1; s = g_s1; width = H1n; }
    else           { h = g_h2; s = g_s2; width = H2n; }
    size_t g = (size_t)blockIdx.x * blockDim.x + threadIdx.x;
    if (g >= (size_t)Bn * width) return;
    const size_t step = (size_t)Bn * width;
    size_t idx = g;
    float v = 0.0f;
    const __half one = __float2half_rn(1.0f);
    const __half zero = __float2half_rn(0.0f);
#pragma unroll 4
    for (int t = 0; t < Tn; t++) {
        float hh = __ldcs(&h[idx]);
        v = v + (hh - v) * 0.5f;
        if (v - 1.0f >= 0.0f) { s[idx] = one; v = 0.0f; }
        else                  { s[idx] = zero; }
        idx += step;
    }
}

// ---------------- output layer: GEMM3 + LIF3 + time-reduce ------------------
__global__ void k_out(const float* __restrict__ Wo, const float* __restrict__ bo,
                      float* __restrict__ out) {
    int warp = (blockIdx.x * blockDim.x + threadIdx.x) >> 5;
    int lane = threadIdx.x & 31;
    if (warp >= Bn) return;
    int b = warp;

    float w[On][8];
#pragma unroll
    for (int k = 0; k < On; k++)
#pragma unroll
        for (int i = 0; i < 8; i++) w[k][i] = Wo[k * H2n + lane + 32 * i];
    float bol[On];
#pragma unroll
    for (int k = 0; k < On; k++) bol[k] = bo[k];

    float vo[On];
    int cnt[On];
#pragma unroll
    for (int k = 0; k < On; k++) { vo[k] = 0.0f; cnt[k] = 0; }

    for (int t = 0; t < Tn; t++) {
        const __half* s = g_s2 + ((size_t)t * Bn + b) * H2n;
        float sv[8];
#pragma unroll
        for (int i = 0; i < 8; i++) sv[i] = __half2float(s[lane + 32 * i]);
        float acc[On];
#pragma unroll
        for (int k = 0; k < On; k++) acc[k] = 0.0f;
#pragma unroll
        for (int i = 0; i < 8; i++)
#pragma unroll
            for (int k = 0; k < On; k++) acc[k] = fmaf(sv[i], w[k][i], acc[k]);
#pragma unroll
        for (int k = 0; k < On; k++) {
#pragma unroll
            for (int off = 16; off > 0; off >>= 1)
                acc[k] += __shfl_down_sync(0xffffffffu, acc[k], off);
        }
        if (lane == 0) {
#pragma unroll
            for (int k = 0; k < On; k++) {
                float o = acc[k] + bol[k];
                vo[k] = vo[k] + (o - vo[k]) * 0.5f;
                if (vo[k] - 1.0f >= 0.0f) { cnt[k]++; vo[k] = 0.0f; }
            }
        }
    }
    if (lane == 0) {
#pragma unroll
        for (int k = 0; k < On; k++)
            out[(size_t)b * On + k] = (float)cnt[k] / 100.0f;
    }
}

// ---------------------------------------------------------------------------
extern "C" void kernel_launch(void* const* d_in, const int* in_sizes, int n_in,
                              void* d_out, int out_size) {
    const float* x  = (const float*)d_in[0];   // (2048, 512, 100)
    const float* W1 = (const float*)d_in[1];   // (512, 512)
    const float* b1 = (const float*)d_in[2];   // (512)
    const float* W2 = (const float*)d_in[3];   // (256, 512)
    const float* b2 = (const float*)d_in[4];   // (256)
    const float* Wo = (const float*)d_in[5];   // (5, 256)
    const float* bo = (const float*)d_in[6];   // (5)
    float* out = (float*)d_out;                // (2048, 5)

    // 0) 2-way fp16 splits of W1, W2
    k_wsplit<1><<<(H1n * Nin + 255) / 256, 256>>>(W1, H1n * Nin);
    k_wsplit<2><<<(H2n * H1n + 255) / 256, 256>>>(W2, H2n * H1n);
    // 1) transpose + 2-way fp16 split x
    k_transpose<<<dim3(Bn, Nin / 32, (Tn + 31) / 32), dim3(32, 8)>>>(x);
    // 2) h1 = x @ W1^T + b1  (fp16x3, 64x64 tiles, high occupancy)
    k_gemm<512, 3, 1><<<dim3(H1n / 64, Mn / 64), 128>>>(b1, g_h1);
    // 3) LIF layer 1 -> s1 (fp16 spikes, exact)
    k_lif<1><<<(Bn * H1n) / 256, 256>>>();
    // 4) h2 = s1 @ W2^T + b2  (fp16x2, 64x64 tiles)
    k_gemm<256, 2, 2><<<dim3(H2n / 64, Mn / 64), 128>>>(b2, g_h2);
    // 5) LIF layer 2 -> s2
    k_lif<2><<<(Bn * H2n) / 256, 256>>>();
    // 6) output layer GEMM + LIF + spike-count reduce
    k_out<<<Bn / 8, 256>>>(Wo, bo, out);
}

// round 15
// speedup vs baseline: 1.4598x; 1.4598x over previous
#include <cuda_runtime.h>
#include <cstdint>

#define Bn   2048
#define Nin  512
#define Tn   100
#define H1n  512
#define H2n  256
#define On   5
#define Mn   (Tn*Bn)   // 204800 rows = (t,b)

// Scratch (static device globals: allocation-free per harness rules)
__device__ float g_xT[(size_t)Mn * Nin];   // xT[(t*B+b)*N + n]
__device__ float g_h1[(size_t)Mn * H1n];   // h1 then (in-place) s1
__device__ float g_h2[(size_t)Mn * H2n];   // h2 (LIF2 fused into k_out)

// ---------------- packed f32x2 helpers (sm_103a full-rate fp32) ------------
__device__ __forceinline__ unsigned long long pk2(float lo, float hi) {
    unsigned long long r;
    asm("mov.b64 %0, {%1, %2};" : "=l"(r) : "f"(lo), "f"(hi));
    return r;
}
__device__ __forceinline__ void upk2(unsigned long long v, float& lo, float& hi) {
    asm("mov.b64 {%0, %1}, %2;" : "=f"(lo), "=f"(hi) : "l"(v));
}
__device__ __forceinline__ unsigned long long fma2(unsigned long long a,
                                                   unsigned long long b,
                                                   unsigned long long c) {
    unsigned long long d;
    asm("fma.rn.f32x2 %0, %1, %2, %3;" : "=l"(d) : "l"(a), "l"(b), "l"(c));
    return d;
}

// ---------------- transpose x (B,N,T) -> xT[(t*B+b)*N + n] -----------------
__global__ void k_transpose(const float* __restrict__ x) {
    __shared__ float tile[32][33];
    int b  = blockIdx.x;
    int n0 = blockIdx.y * 32;
    int t0 = blockIdx.z * 32;
    int tx = threadIdx.x, ty = threadIdx.y;   // 32 x 8
#pragma unroll
    for (int i = 0; i < 4; i++) {
        int n = n0 + ty + i * 8, t = t0 + tx;
        if (t < Tn) tile[ty + i * 8][tx] = x[((size_t)b * Nin + n) * Tn + t];
    }
    __syncthreads();
#pragma unroll
    for (int i = 0; i < 4; i++) {
        int t = t0 + ty + i * 8, n = n0 + tx;
        if (t < Tn) g_xT[((size_t)t * Bn + b) * Nin + n] = tile[tx][ty + i * 8];
    }
}

// ---------------- SGEMM (NT): C[m][n] = sum_k A[m][k]*Bw[n][k] + bias[n] ---
// M = 204800 (multiple of 256), K = 512, N in {512, 256}.
// CTA tile 256x128, 256 threads, thread microtile 16x8 via fma.rn.f32x2.
// FMA-dominant balance: per warp*k, LDS ~10-12 cyc (A is warp-broadcast) vs
// 64 FFMA2; per SM: 8 warps LDS < per-SMSP FMA stream -> fma pipe bound.
__global__ __launch_bounds__(256, 1)
void k_gemm(const float* __restrict__ Bw, const float* __restrict__ bias,
            int ldc, int mode) {
    const float* A;
    float* C;
    if (mode == 1) { A = g_xT; C = g_h1; } else { A = g_h1; C = g_h2; }

    __shared__ float As[16][260];   // [k][m] m=0..255, pad 4
    __shared__ float Bs[16][132];   // [k][n] n=0..127, pad 4

    const int tid = threadIdx.x;
    const int nt = blockIdx.x, mt = blockIdx.y;
    const float* Ab = A  + (size_t)mt * 256 * 512;
    const float* Bb = Bw + (size_t)nt * 128 * 512;

    const int lr = tid >> 2;          // 0..63
    const int lc = (tid & 3) << 2;    // 0,4,8,12
    const int tmr = tid >> 4;         // 0..15 -> m base tmr*16
    const int tn  = tid & 15;         // 0..15 -> n base tn*8

    unsigned long long c2[16][4];
#pragma unroll
    for (int m = 0; m < 16; m++)
#pragma unroll
        for (int p = 0; p < 4; p++) c2[m][p] = 0ull;

    float4 fa[4], fb[2];
    // prologue: load k-tile 0
#pragma unroll
    for (int i = 0; i < 4; i++)
        fa[i] = *(const float4*)(Ab + (size_t)(lr + 64 * i) * 512 + lc);
#pragma unroll
    for (int i = 0; i < 2; i++)
        fb[i] = *(const float4*)(Bb + (size_t)(lr + 64 * i) * 512 + lc);
#pragma unroll
    for (int i = 0; i < 4; i++) {
        As[lc + 0][lr + 64 * i] = fa[i].x; As[lc + 1][lr + 64 * i] = fa[i].y;
        As[lc + 2][lr + 64 * i] = fa[i].z; As[lc + 3][lr + 64 * i] = fa[i].w;
    }
#pragma unroll
    for (int i = 0; i < 2; i++) {
        Bs[lc + 0][lr + 64 * i] = fb[i].x; Bs[lc + 1][lr + 64 * i] = fb[i].y;
        Bs[lc + 2][lr + 64 * i] = fb[i].z; Bs[lc + 3][lr + 64 * i] = fb[i].w;
    }
    __syncthreads();

    for (int kt = 0; kt < 32; kt++) {
        if (kt < 31) {  // prefetch next k-tile into registers
            const int ko = (kt + 1) * 16 + lc;
#pragma unroll
            for (int i = 0; i < 4; i++)
                fa[i] = *(const float4*)(Ab + (size_t)(lr + 64 * i) * 512 + ko);
#pragma unroll
            for (int i = 0; i < 2; i++)
                fb[i] = *(const float4*)(Bb + (size_t)(lr + 64 * i) * 512 + ko);
        }
#pragma unroll
        for (int k = 0; k < 16; k++) {
            float4 b0 = *(const float4*)&Bs[k][tn * 8];
            float4 b1 = *(const float4*)&Bs[k][tn * 8 + 4];
            unsigned long long bb[4] = { pk2(b0.x, b0.y), pk2(b0.z, b0.w),
                                         pk2(b1.x, b1.y), pk2(b1.z, b1.w) };
            float4 a0 = *(const float4*)&As[k][tmr * 16];
            float4 a1 = *(const float4*)&As[k][tmr * 16 + 4];
            float4 a2 = *(const float4*)&As[k][tmr * 16 + 8];
            float4 a3 = *(const float4*)&As[k][tmr * 16 + 12];
            float av[16] = { a0.x, a0.y, a0.z, a0.w, a1.x, a1.y, a1.z, a1.w,
                             a2.x, a2.y, a2.z, a2.w, a3.x, a3.y, a3.z, a3.w };
#pragma unroll
            for (int m = 0; m < 16; m++) {
                unsigned long long am = pk2(av[m], av[m]);
#pragma unroll
                for (int p = 0; p < 4; p++) c2[m][p] = fma2(am, bb[p], c2[m][p]);
            }
        }
        if (kt < 31) {
            __syncthreads();
#pragma unroll
            for (int i = 0; i < 4; i++) {
                As[lc + 0][lr + 64 * i] = fa[i].x; As[lc + 1][lr + 64 * i] = fa[i].y;
                As[lc + 2][lr + 64 * i] = fa[i].z; As[lc + 3][lr + 64 * i] = fa[i].w;
            }
#pragma unroll
            for (int i = 0; i < 2; i++) {
                Bs[lc + 0][lr + 64 * i] = fb[i].x; Bs[lc + 1][lr + 64 * i] = fb[i].y;
                Bs[lc + 2][lr + 64 * i] = fb[i].z; Bs[lc + 3][lr + 64 * i] = fb[i].w;
            }
            __syncthreads();
        }
    }

    // epilogue: add bias, store
    float bv[8];
#pragma unroll
    for (int p = 0; p < 8; p++) bv[p] = bias[nt * 128 + tn * 8 + p];
    float* Cb = C + (size_t)(mt * 256 + tmr * 16) * ldc + nt * 128 + tn * 8;
#pragma unroll
    for (int m = 0; m < 16; m++) {
#pragma unroll
        for (int p = 0; p < 4; p++) {
            float x0, x1;
            upk2(c2[m][p], x0, x1);
            float2 o;
            o.x = x0 + bv[2 * p];
            o.y = x1 + bv[2 * p + 1];
            *(float2*)(Cb + (size_t)m * ldc + 2 * p) = o;
        }
    }
}

// ---------------- LIF layer 1 over time (in-place h1 -> spikes) ------------
__global__ void k_lif1() {
    size_t g = (size_t)blockIdx.x * blockDim.x + threadIdx.x;
    if (g >= (size_t)Bn * H1n) return;
    const size_t step = (size_t)Bn * H1n;
    size_t idx = g;
    float v = 0.0f;
#pragma unroll 4
    for (int t = 0; t < Tn; t++) {
        float h = g_h1[idx];
        v = v + (h - v) * 0.5f;          // tau = 2.0
        float s;
        if (v - 1.0f >= 0.0f) { s = 1.0f; v = 0.0f; }
        else                  { s = 0.0f; }
        g_h1[idx] = s;
        idx += step;
    }
}

// ---------------- output: LIF2 + GEMM3 + LIF3 + time-reduce (fused) --------
// One warp per batch row. v2 recurrence for 8 neurons lives in lane regs;
// s2 never materialized. Wo (5x256) in registers, vo state in lane 0.
__global__ void k_out(const float* __restrict__ Wo, const float* __restrict__ bo,
                      float* __restrict__ out) {
    int warp = (blockIdx.x * blockDim.x + threadIdx.x) >> 5;
    int lane = threadIdx.x & 31;
    if (warp >= Bn) return;
    int b = warp;

    float w[On][8];
#pragma unroll
    for (int k = 0; k < On; k++)
#pragma unroll
        for (int i = 0; i < 8; i++) w[k][i] = Wo[k * H2n + lane + 32 * i];
    float bol[On];
#pragma unroll
    for (int k = 0; k < On; k++) bol[k] = bo[k];

    float v2[8];
#pragma unroll
    for (int i = 0; i < 8; i++) v2[i] = 0.0f;

    float vo[On];
    int cnt[On];
#pragma unroll
    for (int k = 0; k < On; k++) { vo[k] = 0.0f; cnt[k] = 0; }

    for (int t = 0; t < Tn; t++) {
        const float* h = g_h2 + ((size_t)t * Bn + b) * H2n;
        float sv[8];
#pragma unroll
        for (int i = 0; i < 8; i++) {
            float hh = __ldcs(&h[lane + 32 * i]);
            v2[i] = v2[i] + (hh - v2[i]) * 0.5f;      // LIF2 fused
            if (v2[i] - 1.0f >= 0.0f) { sv[i] = 1.0f; v2[i] = 0.0f; }
            else                      { sv[i] = 0.0f; }
        }
        float acc[On];
#pragma unroll
        for (int k = 0; k < On; k++) acc[k] = 0.0f;
#pragma unroll
        for (int i = 0; i < 8; i++)
#pragma unroll
            for (int k = 0; k < On; k++) acc[k] = fmaf(sv[i], w[k][i], acc[k]);
#pragma unroll
        for (int k = 0; k < On; k++) {
#pragma unroll
            for (int off = 16; off > 0; off >>= 1)
                acc[k] += __shfl_down_sync(0xffffffffu, acc[k], off);
        }
        if (lane == 0) {
#pragma unroll
            for (int k = 0; k < On; k++) {
                float o = acc[k] + bol[k];
                vo[k] = vo[k] + (o - vo[k]) * 0.5f;
                if (vo[k] - 1.0f >= 0.0f) { cnt[k]++; vo[k] = 0.0f; }
            }
        }
    }
    if (lane == 0) {
#pragma unroll
        for (int k = 0; k < On; k++)
            out[(size_t)b * On + k] = (float)cnt[k] / 100.0f;
    }
}

// ---------------------------------------------------------------------------
extern "C" void kernel_launch(void* const* d_in, const int* in_sizes, int n_in,
                              void* d_out, int out_size) {
    const float* x  = (const float*)d_in[0];   // (2048, 512, 100)
    const float* W1 = (const float*)d_in[1];   // (512, 512)
    const float* b1 = (const float*)d_in[2];   // (512)
    const float* W2 = (const float*)d_in[3];   // (256, 512)
    const float* b2 = (const float*)d_in[4];   // (256)
    const float* Wo = (const float*)d_in[5];   // (5, 256)
    const float* bo = (const float*)d_in[6];   // (5)
    float* out = (float*)d_out;                // (2048, 5)

    // 1) transpose x -> xT[(t*B+b)*N + n]
    k_transpose<<<dim3(Bn, Nin / 32, (Tn + 31) / 32), dim3(32, 8)>>>(x);
    // 2) h1 = xT @ W1^T + b1   (256x128 CTA tiles, 16x8 microtile)
    k_gemm<<<dim3(H1n / 128, Mn / 256), 256>>>(W1, b1, H1n, 1);
    // 3) LIF layer 1 (in-place h1 -> s1, fp32)
    k_lif1<<<(Bn * H1n) / 256, 256>>>();
    // 4) h2 = s1 @ W2^T + b2
    k_gemm<<<dim3(H2n / 128, Mn / 256), 256>>>(W2, b2, H2n, 2);
    // 5) fused LIF2 + output GEMM + LIF3 + spike-count reduce
    k_out<<<Bn / 8, 256>>>(Wo, bo, out);
}

// round 17
// speedup vs baseline: 1.5029x; 1.0295x over previous
#include <cuda_runtime.h>
#include <cstdint>

#define Bn   2048
#define Nin  512
#define Tn   100
#define H1n  512
#define H2n  256
#define On   5
#define Mn   (Tn*Bn)   // 204800 rows = (t,b)

// Scratch (static device globals: allocation-free per harness rules)
__device__ float g_xT[(size_t)Mn * Nin];   // xT[(t*B+b)*N + n]
__device__ float g_h1[(size_t)Mn * H1n];   // h1 then (in-place) s1
__device__ float g_h2[(size_t)Mn * H2n];   // h2 (LIF2 fused into k_out)

// ---------------- packed f32x2 helpers (sm_103a full-rate fp32) ------------
__device__ __forceinline__ unsigned long long pk2(float lo, float hi) {
    unsigned long long r;
    asm("mov.b64 %0, {%1, %2};" : "=l"(r) : "f"(lo), "f"(hi));
    return r;
}
__device__ __forceinline__ void upk2(unsigned long long v, float& lo, float& hi) {
    asm("mov.b64 {%0, %1}, %2;" : "=f"(lo), "=f"(hi) : "l"(v));
}
__device__ __forceinline__ unsigned long long fma2(unsigned long long a,
                                                   unsigned long long b,
                                                   unsigned long long c) {
    unsigned long long d;
    asm("fma.rn.f32x2 %0, %1, %2, %3;" : "=l"(d) : "l"(a), "l"(b), "l"(c));
    return d;
}

// ---------------- transpose x (B,N,T) -> xT[(t*B+b)*N + n] -----------------
__global__ void k_transpose(const float* __restrict__ x) {
    __shared__ float tile[32][33];
    int b  = blockIdx.x;
    int n0 = blockIdx.y * 32;
    int t0 = blockIdx.z * 32;
    int tx = threadIdx.x, ty = threadIdx.y;   // 32 x 8
#pragma unroll
    for (int i = 0; i < 4; i++) {
        int n = n0 + ty + i * 8, t = t0 + tx;
        if (t < Tn) tile[ty + i * 8][tx] = x[((size_t)b * Nin + n) * Tn + t];
    }
    __syncthreads();
#pragma unroll
    for (int i = 0; i < 4; i++) {
        int t = t0 + ty + i * 8, n = n0 + tx;
        if (t < Tn) g_xT[((size_t)t * Bn + b) * Nin + n] = tile[tx][ty + i * 8];
    }
}

// ---------------- SGEMM (NT): C[m][n] = sum_k A[m][k]*Bw[n][k] + bias[n] ---
// M = 204800 (multiple of 256), K = 512, N in {512, 256}.
// CTA tile 256x128, 256 threads, thread microtile 16x8 via fma.rn.f32x2.
// Double-buffered smem: ONE __syncthreads per k-tile (was 2).
#define AS_F 4160   // 16*260 floats per A stage
#define BS_F 2112   // 16*132 floats per B stage
#define GEMM_SMEM ((2 * (AS_F + BS_F)) * 4)   // 50176 bytes

__global__ __launch_bounds__(256, 1)
void k_gemm(const float* __restrict__ Bw, const float* __restrict__ bias,
            int ldc, int mode) {
    const float* A;
    float* C;
    if (mode == 1) { A = g_xT; C = g_h1; } else { A = g_h1; C = g_h2; }

    extern __shared__ float sm[];
    float* AsBase = sm;                 // 2 stages of [16][260]
    float* BsBase = sm + 2 * AS_F;      // 2 stages of [16][132]

    const int tid = threadIdx.x;
    const int nt = blockIdx.x, mt = blockIdx.y;
    const float* Ab = A  + (size_t)mt * 256 * 512;
    const float* Bb = Bw + (size_t)nt * 128 * 512;

    const int lr = tid >> 2;          // 0..63
    const int lc = (tid & 3) << 2;    // 0,4,8,12
    const int tmr = tid >> 4;         // 0..15 -> m base tmr*16
    const int tn  = tid & 15;         // 0..15 -> n base tn*8

    unsigned long long c2[16][4];
#pragma unroll
    for (int m = 0; m < 16; m++)
#pragma unroll
        for (int p = 0; p < 4; p++) c2[m][p] = 0ull;

    float4 fa[4], fb[2];

    auto stage_store = [&](int buf) {
        float* As = AsBase + buf * AS_F;
        float* Bs = BsBase + buf * BS_F;
#pragma unroll
        for (int i = 0; i < 4; i++) {
            As[(lc + 0) * 260 + lr + 64 * i] = fa[i].x;
            As[(lc + 1) * 260 + lr + 64 * i] = fa[i].y;
            As[(lc + 2) * 260 + lr + 64 * i] = fa[i].z;
            As[(lc + 3) * 260 + lr + 64 * i] = fa[i].w;
        }
#pragma unroll
        for (int i = 0; i < 2; i++) {
            Bs[(lc + 0) * 132 + lr + 64 * i] = fb[i].x;
            Bs[(lc + 1) * 132 + lr + 64 * i] = fb[i].y;
            Bs[(lc + 2) * 132 + lr + 64 * i] = fb[i].z;
            Bs[(lc + 3) * 132 + lr + 64 * i] = fb[i].w;
        }
    };

    // prologue: load k-tile 0 -> stage 0
#pragma unroll
    for (int i = 0; i < 4; i++)
        fa[i] = *(const float4*)(Ab + (size_t)(lr + 64 * i) * 512 + lc);
#pragma unroll
    for (int i = 0; i < 2; i++)
        fb[i] = *(const float4*)(Bb + (size_t)(lr + 64 * i) * 512 + lc);
    stage_store(0);
    __syncthreads();

    for (int kt = 0; kt < 32; kt++) {
        const int buf = kt & 1;
        if (kt < 31) {  // prefetch next k-tile into registers
            const int ko = (kt + 1) * 16 + lc;
#pragma unroll
            for (int i = 0; i < 4; i++)
                fa[i] = *(const float4*)(Ab + (size_t)(lr + 64 * i) * 512 + ko);
#pragma unroll
            for (int i = 0; i < 2; i++)
                fb[i] = *(const float4*)(Bb + (size_t)(lr + 64 * i) * 512 + ko);
        }
        const float* As = AsBase + buf * AS_F;
        const float* Bs = BsBase + buf * BS_F;
#pragma unroll
        for (int k = 0; k < 16; k++) {
            float4 b0 = *(const float4*)&Bs[k * 132 + tn * 8];
            float4 b1 = *(const float4*)&Bs[k * 132 + tn * 8 + 4];
            unsigned long long bb[4] = { pk2(b0.x, b0.y), pk2(b0.z, b0.w),
                                         pk2(b1.x, b1.y), pk2(b1.z, b1.w) };
            float4 a0 = *(const float4*)&As[k * 260 + tmr * 16];
            float4 a1 = *(const float4*)&As[k * 260 + tmr * 16 + 4];
            float4 a2 = *(const float4*)&As[k * 260 + tmr * 16 + 8];
            float4 a3 = *(const float4*)&As[k * 260 + tmr * 16 + 12];
            float av[16] = { a0.x, a0.y, a0.z, a0.w, a1.x, a1.y, a1.z, a1.w,
                             a2.x, a2.y, a2.z, a2.w, a3.x, a3.y, a3.z, a3.w };
#pragma unroll
            for (int m = 0; m < 16; m++) {
                unsigned long long am = pk2(av[m], av[m]);
#pragma unroll
                for (int p = 0; p < 4; p++) c2[m][p] = fma2(am, bb[p], c2[m][p]);
            }
        }
        if (kt < 31) {
            stage_store(buf ^ 1);   // write OTHER stage: no pre-store sync needed
            __syncthreads();        // single barrier: stores visible for next iter
        }
    }

    // epilogue: add bias, store
    float bv[8];
#pragma unroll
    for (int p = 0; p < 8; p++) bv[p] = bias[nt * 128 + tn * 8 + p];
    float* Cb = C + (size_t)(mt * 256 + tmr * 16) * ldc + nt * 128 + tn * 8;
#pragma unroll
    for (int m = 0; m < 16; m++) {
#pragma unroll
        for (int p = 0; p < 4; p++) {
            float x0, x1;
            upk2(c2[m][p], x0, x1);
            float2 o;
            o.x = x0 + bv[2 * p];
            o.y = x1 + bv[2 * p + 1];
            *(float2*)(Cb + (size_t)m * ldc + 2 * p) = o;
        }
    }
}

// ---------------- LIF layer 1 over time (in-place h1 -> spikes) ------------
__global__ void k_lif1() {
    size_t g = (size_t)blockIdx.x * blockDim.x + threadIdx.x;
    if (g >= (size_t)Bn * H1n) return;
    const size_t step = (size_t)Bn * H1n;
    size_t idx = g;
    float v = 0.0f;
#pragma unroll 4
    for (int t = 0; t < Tn; t++) {
        float h = g_h1[idx];
        v = v + (h - v) * 0.5f;          // tau = 2.0
        float s;
        if (v - 1.0f >= 0.0f) { s = 1.0f; v = 0.0f; }
        else                  { s = 0.0f; }
        g_h1[idx] = s;
        idx += step;
    }
}

// ---------------- output: LIF2 + GEMM3 + LIF3 + time-reduce (fused) --------
__global__ void k_out(const float* __restrict__ Wo, const float* __restrict__ bo,
                      float* __restrict__ out) {
    int warp = (blockIdx.x * blockDim.x + threadIdx.x) >> 5;
    int lane = threadIdx.x & 31;
    if (warp >= Bn) return;
    int b = warp;

    float w[On][8];
#pragma unroll
    for (int k = 0; k < On; k++)
#pragma unroll
        for (int i = 0; i < 8; i++) w[k][i] = Wo[k * H2n + lane + 32 * i];
    float bol[On];
#pragma unroll
    for (int k = 0; k < On; k++) bol[k] = bo[k];

    float v2[8];
#pragma unroll
    for (int i = 0; i < 8; i++) v2[i] = 0.0f;

    float vo[On];
    int cnt[On];
#pragma unroll
    for (int k = 0; k < On; k++) { vo[k] = 0.0f; cnt[k] = 0; }

    for (int t = 0; t < Tn; t++) {
        const float* h = g_h2 + ((size_t)t * Bn + b) * H2n;
        float sv[8];
#pragma unroll
        for (int i = 0; i < 8; i++) {
            float hh = __ldcs(&h[lane + 32 * i]);
            v2[i] = v2[i] + (hh - v2[i]) * 0.5f;      // LIF2 fused
            if (v2[i] - 1.0f >= 0.0f) { sv[i] = 1.0f; v2[i] = 0.0f; }
            else                      { sv[i] = 0.0f; }
        }
        float acc[On];
#pragma unroll
        for (int k = 0; k < On; k++) acc[k] = 0.0f;
#pragma unroll
        for (int i = 0; i < 8; i++)
#pragma unroll
            for (int k = 0; k < On; k++) acc[k] = fmaf(sv[i], w[k][i], acc[k]);
#pragma unroll
        for (int k = 0; k < On; k++) {
#pragma unroll
            for (int off = 16; off > 0; off >>= 1)
                acc[k] += __shfl_down_sync(0xffffffffu, acc[k], off);
        }
        if (lane == 0) {
#pragma unroll
            for (int k = 0; k < On; k++) {
                float o = acc[k] + bol[k];
                vo[k] = vo[k] + (o - vo[k]) * 0.5f;
                if (vo[k] - 1.0f >= 0.0f) { cnt[k]++; vo[k] = 0.0f; }
            }
        }
    }
    if (lane == 0) {
#pragma unroll
        for (int k = 0; k < On; k++)
            out[(size_t)b * On + k] = (float)cnt[k] / 100.0f;
    }
}

// ---------------------------------------------------------------------------
extern "C" void kernel_launch(void* const* d_in, const int* in_sizes, int n_in,
                              void* d_out, int out_size) {
    const float* x  = (const float*)d_in[0];   // (2048, 512, 100)
    const float* W1 = (const float*)d_in[1];   // (512, 512)
    const float* b1 = (const float*)d_in[2];   // (512)
    const float* W2 = (const float*)d_in[3];   // (256, 512)
    const float* b2 = (const float*)d_in[4];   // (256)
    const float* Wo = (const float*)d_in[5];   // (5, 256)
    const float* bo = (const float*)d_in[6];   // (5)
    float* out = (float*)d_out;                // (2048, 5)

    static bool attr_done = false;
    if (!attr_done) {
        cudaFuncSetAttribute(k_gemm, cudaFuncAttributeMaxDynamicSharedMemorySize,
                             GEMM_SMEM);
        attr_done = true;
    }

    // 1) transpose x -> xT[(t*B+b)*N + n]
    k_transpose<<<dim3(Bn, Nin / 32, (Tn + 31) / 32), dim3(32, 8)>>>(x);
    // 2) h1 = xT @ W1^T + b1   (256x128 CTA tiles, 16x8 microtile, 1 sync/iter)
    k_gemm<<<dim3(H1n / 128, Mn / 256), 256, GEMM_SMEM>>>(W1, b1, H1n, 1);
    // 3) LIF layer 1 (in-place h1 -> s1, fp32)
    k_lif1<<<(Bn * H1n) / 256, 256>>>();
    // 4) h2 = s1 @ W2^T + b2
    k_gemm<<<dim3(H2n / 128, Mn / 256), 256, GEMM_SMEM>>>(W2, b2, H2n, 2);
    // 5) fused LIF2 + output GEMM + LIF3 + spike-count reduce
    k_out<<<Bn / 8, 256>>>(Wo, bo, out);
}